// round 13
// baseline (speedup 1.0000x reference)
#include <cuda_runtime.h>
#include <cuda_fp16.h>
#include <cstdint>

#define EPS  1e-6f
#define KK   1024
#define DDIM 256

// ---------------- helpers ----------------------------------------------------
__device__ __forceinline__ uint32_t smem_u32(const void* p) {
    uint32_t r;
    asm("{ .reg .u64 t; cvta.to.shared.u64 t, %1; cvt.u32.u64 %0, t; }"
        : "=r"(r) : "l"(p));
    return r;
}
__device__ __forceinline__ void ldsm_x4(uint32_t* r, uint32_t addr) {
    asm volatile("ldmatrix.sync.aligned.m8n8.x4.shared.b16 {%0,%1,%2,%3}, [%4];"
                 : "=r"(r[0]), "=r"(r[1]), "=r"(r[2]), "=r"(r[3]) : "r"(addr));
}
__device__ __forceinline__ void mma_f16(float* d, const uint32_t* a,
                                        uint32_t b0, uint32_t b1) {
    asm volatile(
        "mma.sync.aligned.m16n8k16.row.col.f32.f16.f16.f32 "
        "{%0,%1,%2,%3}, {%4,%5,%6,%7}, {%8,%9}, {%0,%1,%2,%3};"
        : "+f"(d[0]), "+f"(d[1]), "+f"(d[2]), "+f"(d[3])
        : "r"(a[0]), "r"(a[1]), "r"(a[2]), "r"(a[3]), "r"(b0), "r"(b1));
}
__device__ __forceinline__ uint2 cvt4(float4 f) {
    __half2 h0 = __floats2half2_rn(f.x, f.y);
    __half2 h1 = __floats2half2_rn(f.z, f.w);
    uint2 v;
    v.x = *(uint32_t*)&h0;
    v.y = *(uint32_t*)&h1;
    return v;
}
__device__ __forceinline__ float dot4(float4 u, float4 v) {
    return u.x*v.x + u.y*v.y + u.z*v.z + u.w*v.w;
}

// ============================================================================
// FUSED kernel: fp32 load -> fp16 convert -> dual GEMM (mma.sync) -> logits.
//   CTA: 64(m) x 16(n), 8 warps 4x2, warp tile 16x8. 512 CTAs.
//   Chunk KC=64; stage = Xh(8K) + Ph(2K) + Ah(2K) = 12KB; 2 stages.
//   Stats (x2, p2, pa, na2) computed inline from the fp32 data during load.
//   P and A b-fragments fetched with ONE ldmatrix.x4 (mat 0-1 = p, 2-3 = a).
// ============================================================================
#define MT    64
#define NT    16
#define KC    64
#define NCH   (DDIM / KC)   // 4
#define XOFF  0
#define POFF  8192
#define AOFF  10240
#define STAGE 12288

__global__ __launch_bounds__(256)
void hyp_fused_kernel(const float* __restrict__ x,
                      const float* __restrict__ p,
                      const float* __restrict__ a,
                      float* __restrict__ out)
{
    __shared__ char buf[2 * STAGE];
    __shared__ float sx2[MT], sp2[NT], spa[NT], sna2[NT];
    const uint32_t smb = smem_u32(buf);

    const int tid  = threadIdx.x;
    const int wid  = tid >> 5;
    const int lane = tid & 31;
    const int k0   = blockIdx.x * NT;
    const int b0   = blockIdx.y * MT;

    // ---- loader indices ------------------------------------------------------
    // x: 64 rows; thread t handles row t>>2, 4 float4 segs (t&3)*4+j per chunk
    const int xr = tid >> 2;
    const int xc = tid & 3;
    const float* xsrc = x + (size_t)(b0 + xr) * DDIM + xc * 16;
    uint32_t xdst[4];
    #pragma unroll
    for (int j = 0; j < 4; j++) {
        uint32_t col = xc * 32 + j * 8;                 // bytes (fp16)
        xdst[j] = XOFF + xr * 128 + (col ^ ((xr & 7) << 4));
    }
    // p/a: 16 rows; thread t handles row t>>4, float4 seg t&15 per chunk
    const int pr = tid >> 4;
    const int pc = tid & 15;
    const float* psrc = p + (size_t)(k0 + pr) * DDIM + pc * 4;
    const float* asrc = a + (size_t)(k0 + pr) * DDIM + pc * 4;
    const uint32_t pdst = POFF + pr * 128 + (((uint32_t)pc * 8) ^ ((pr & 7) << 4));
    const uint32_t adst = pdst + (AOFF - POFF);

    float x2p = 0.f, p2p = 0.f, pap = 0.f, na2p = 0.f;
    float4 fx[4], fp4, fa4;

    auto fetch = [&](int c) {
        const int c0 = c * KC;
        #pragma unroll
        for (int j = 0; j < 4; j++)
            fx[j] = *(const float4*)(xsrc + c0 + j * 4);
        fp4 = *(const float4*)(psrc + c0);
        fa4 = *(const float4*)(asrc + c0);
    };
    auto cvst = [&](int s) {   // convert + stats + store (called once per chunk)
        char* bb = buf + s * STAGE;
        #pragma unroll
        for (int j = 0; j < 4; j++) {
            x2p += dot4(fx[j], fx[j]);
            *(uint2*)(bb + xdst[j]) = cvt4(fx[j]);
        }
        p2p  += dot4(fp4, fp4);
        pap  += dot4(fp4, fa4);
        na2p += dot4(fa4, fa4);
        *(uint2*)(bb + pdst) = cvt4(fp4);
        *(uint2*)(bb + adst) = cvt4(fa4);
    };

    // ---- warp tiling / ldsm addressing ---------------------------------------
    const int wm = (wid >> 1) * 16;          // 4 m-warps
    const int wn = (wid & 1)  * 8;           // 2 n-warps
    // A (x4): m16k16 per kstep
    const int g  = lane >> 3;
    const int r  = lane & 7;
    const int rowadd = (g & 1) * 8 + r;
    const int cadd   = (g >> 1) * 16;        // k8 byte offset
    const uint32_t axor  = (rowadd & 7) << 4;
    const uint32_t xterm = XOFF + (wm + rowadd) * 128;
    // B combined (x4): mat0-1 = p (k0-7, k8-15), mat2-3 = a
    const int brow = lane & 7;
    const uint32_t bko  = (uint32_t)(g & 1) * 16;
    const uint32_t bxor = (uint32_t)brow << 4;
    const uint32_t bterm = POFF + (uint32_t)(g >> 1) * (AOFF - POFF)
                         + (wn + brow) * 128;

    float accP[4] = {}, accA[4] = {};

    // ---- mainloop: register-staged double buffer, 1 sync per chunk -----------
    fetch(0);
    cvst(0);
    __syncthreads();

    for (int c = 0; c < NCH; c++) {
        if (c + 1 < NCH) fetch(c + 1);   // LDG overlaps GEMM below

        const uint32_t sb = smb + (c & 1) * STAGE;
        #pragma unroll
        for (int ks = 0; ks < 4; ks++) {
            uint32_t axh[4], bpa[4];
            ldsm_x4(axh, sb + xterm + ((uint32_t)(32 * ks + cadd) ^ axor));
            ldsm_x4(bpa, sb + bterm + (((uint32_t)(32 * ks) + bko) ^ bxor));
            mma_f16(accP, axh, bpa[0], bpa[1]);
            mma_f16(accA, axh, bpa[2], bpa[3]);
        }

        if (c + 1 < NCH) {
            // buffer (c+1)&1 was last read in chunk c-1; all warps passed the
            // sync at end of chunk c-1, so overwriting it now is safe.
            cvst((c + 1) & 1);
            __syncthreads();
        }
    }

    // ---- stats reduction ------------------------------------------------------
    x2p += __shfl_xor_sync(~0u, x2p, 1);
    x2p += __shfl_xor_sync(~0u, x2p, 2);
    if ((tid & 3) == 0) sx2[xr] = x2p;
    #pragma unroll
    for (int m = 1; m <= 8; m <<= 1) {
        p2p  += __shfl_xor_sync(~0u, p2p,  m);
        pap  += __shfl_xor_sync(~0u, pap,  m);
        na2p += __shfl_xor_sync(~0u, na2p, m);
    }
    if ((tid & 15) == 0) { sp2[pr] = p2p; spa[pr] = pap; sna2[pr] = na2p; }
    __syncthreads();

    // ---- epilogue: hyperbolic MLR logit ---------------------------------------
    #pragma unroll
    for (int h = 0; h < 2; h++) {
        const int mloc = wm + h * 8 + (lane >> 2);
        const float x2 = sx2[mloc];
        const int kloc = wn + (lane & 3) * 2;
        float2 res;
        float* rr = (float*)&res;
        #pragma unroll
        for (int q = 0; q < 2; q++) {
            const float xp  = accP[h * 2 + q];
            const float xa  = accA[h * 2 + q];
            const float p2  = sp2[kloc + q];
            const float pa  = spa[kloc + q];
            const float na2 = sna2[kloc + q];

            float beta  = 1.f - p2;
            float alpha = -(1.f - 2.f * xp + x2);
            float den   = 1.f - 2.f * xp + p2 * x2 + EPS;
            float inv   = 1.f / den;
            float z2 = (alpha*alpha*p2 + 2.f*alpha*beta*xp + beta*beta*x2)
                       * inv * inv;
            float za = beta * (alpha * pa + beta * xa) * inv;
            float na = beta * sqrtf(na2);
            float lam = 2.f / (beta + EPS);
            float tt = 2.f * za / ((1.f - z2) * na + EPS);
            rr[q] = lam * na * asinhf(tt);
        }
        *(float2*)(out + (size_t)(b0 + mloc) * KK + k0 + kloc) = res;
    }
}

// ============================================================================
extern "C" void kernel_launch(void* const* d_in, const int* in_sizes, int n_in,
                              void* d_out, int out_size)
{
    const float* x = (const float*)d_in[0];
    const float* p = (const float*)d_in[1];
    const float* a = (const float*)d_in[2];
    float* out = (float*)d_out;

    const int B = in_sizes[0] / DDIM;   // 512
    dim3 grid(KK / NT, B / MT);         // (64, 8) = 512 CTAs
    hyp_fused_kernel<<<grid, 256>>>(x, p, a, out);
}

// round 14
// speedup vs baseline: 1.2941x; 1.2941x over previous
#include <cuda_runtime.h>
#include <cuda_fp16.h>
#include <cstdint>

#define EPS  1e-6f
#define BB   512
#define KK   1024
#define DDIM 256

// ---------------- scratch (device globals: allocation-free) -----------------
__device__ __half g_xh[BB * DDIM];                    // fp16(x)
__device__ __half g_ph[KK * DDIM], g_ah[KK * DDIM];   // fp16(p), fp16(a)
__device__ float g_x2[BB], g_p2[KK], g_pa[KK], g_na2[KK];

// ---------------- helpers ----------------------------------------------------
__device__ __forceinline__ uint32_t smem_u32(const void* p) {
    uint32_t r;
    asm("{ .reg .u64 t; cvta.to.shared.u64 t, %1; cvt.u32.u64 %0, t; }"
        : "=r"(r) : "l"(p));
    return r;
}
__device__ __forceinline__ void ldsm_x4(uint32_t* r, uint32_t addr) {
    asm volatile("ldmatrix.sync.aligned.m8n8.x4.shared.b16 {%0,%1,%2,%3}, [%4];"
                 : "=r"(r[0]), "=r"(r[1]), "=r"(r[2]), "=r"(r[3]) : "r"(addr));
}
__device__ __forceinline__ void mma_f16(float* d, const uint32_t* a,
                                        uint32_t b0, uint32_t b1) {
    asm volatile(
        "mma.sync.aligned.m16n8k16.row.col.f32.f16.f16.f32 "
        "{%0,%1,%2,%3}, {%4,%5,%6,%7}, {%8,%9}, {%0,%1,%2,%3};"
        : "+f"(d[0]), "+f"(d[1]), "+f"(d[2]), "+f"(d[3])
        : "r"(a[0]), "r"(a[1]), "r"(a[2]), "r"(a[3]), "r"(b0), "r"(b1));
}
__device__ __forceinline__ void cp16(uint32_t dst, const void* src) {
    asm volatile("cp.async.cg.shared.global [%0], [%1], 16;"
                 :: "r"(dst), "l"(src) : "memory");
}
#define CP_COMMIT() asm volatile("cp.async.commit_group;" ::: "memory")
#define CP_WAIT(n)  asm volatile("cp.async.wait_group %0;" :: "n"(n) : "memory")

// ============================================================================
// Kernel 1: fp32 -> fp16 conversion + exact fp32 stats. One warp per row.
// ============================================================================
__device__ __forceinline__ uint32_t pack2h(float a, float b) {
    __half2 h = __floats2half2_rn(a, b);
    return *(uint32_t*)&h;
}

__global__ __launch_bounds__(256)
void conv_stats_kernel(const float* __restrict__ x,
                       const float* __restrict__ p,
                       const float* __restrict__ a)
{
    const int w    = blockIdx.x * 8 + (threadIdx.x >> 5);
    const int lane = threadIdx.x & 31;
    if (w < BB) {
        const int r = w;
        float f[8];
        *(float4*)&f[0] = *(const float4*)(x + r * DDIM + lane * 8);
        *(float4*)&f[4] = *(const float4*)(x + r * DDIM + lane * 8 + 4);
        uint4 hi;
        uint32_t* hv = (uint32_t*)&hi;
        float x2 = 0.f;
        #pragma unroll
        for (int i = 0; i < 4; i++) {
            hv[i] = pack2h(f[2*i], f[2*i+1]);
            x2 += f[2*i]*f[2*i] + f[2*i+1]*f[2*i+1];
        }
        *(uint4*)(g_xh + r * DDIM + lane * 8) = hi;
        #pragma unroll
        for (int m = 16; m; m >>= 1) x2 += __shfl_xor_sync(~0u, x2, m);
        if (lane == 0) g_x2[r] = x2;
    } else {
        const int r = w - BB;
        float fp[8], fa[8];
        *(float4*)&fp[0] = *(const float4*)(p + r * DDIM + lane * 8);
        *(float4*)&fp[4] = *(const float4*)(p + r * DDIM + lane * 8 + 4);
        *(float4*)&fa[0] = *(const float4*)(a + r * DDIM + lane * 8);
        *(float4*)&fa[4] = *(const float4*)(a + r * DDIM + lane * 8 + 4);
        uint4 hp, ha;
        uint32_t* pv = (uint32_t*)&hp;
        uint32_t* av = (uint32_t*)&ha;
        float p2 = 0.f, pa = 0.f, na2 = 0.f;
        #pragma unroll
        for (int i = 0; i < 4; i++) {
            pv[i] = pack2h(fp[2*i], fp[2*i+1]);
            av[i] = pack2h(fa[2*i], fa[2*i+1]);
            p2  += fp[2*i]*fp[2*i] + fp[2*i+1]*fp[2*i+1];
            pa  += fp[2*i]*fa[2*i] + fp[2*i+1]*fa[2*i+1];
            na2 += fa[2*i]*fa[2*i] + fa[2*i+1]*fa[2*i+1];
        }
        *(uint4*)(g_ph + r * DDIM + lane * 8) = hp;
        *(uint4*)(g_ah + r * DDIM + lane * 8) = ha;
        #pragma unroll
        for (int m = 16; m; m >>= 1) {
            p2  += __shfl_xor_sync(~0u, p2,  m);
            pa  += __shfl_xor_sync(~0u, pa,  m);
            na2 += __shfl_xor_sync(~0u, na2, m);
        }
        if (lane == 0) { g_p2[r] = p2; g_pa[r] = pa; g_na2[r] = na2; }
    }
}

// ============================================================================
// Kernel 2: dual fp16 GEMM (mma.sync), 3-stage cp.async, 1 sync per chunk.
//   CTA: 64(m) x 16(n), 8 warps 4x2, warp tile 16x8. 512 CTAs, ~4/SM.
//   Chunk KC=64; stage = Xh(8K) + Ph(2K) + Ah(2K) = 12KB; 3 stages = 36KB.
//   Refill is issued IMMEDIATELY after the top-of-chunk sync (target stage
//   was last read two chunks ago) -> loads get a 2-chunk window to land.
// ============================================================================
#define MT    64
#define NT    16
#define KC    64
#define NCH   (DDIM / KC)   // 4
#define XHOFF 0
#define PHOFF 8192
#define AHOFF 10240
#define STAGE 12288
#define SMEM2 (3 * STAGE)   // 36864

__global__ __launch_bounds__(256)
void hyp_hmma_kernel(float* __restrict__ out)
{
    extern __shared__ char smem[];
    const uint32_t smb = smem_u32(smem);

    const int tid  = threadIdx.x;
    const int wid  = tid >> 5;
    const int lane = tid & 31;
    const int k0   = blockIdx.x * NT;
    const int b0   = blockIdx.y * MT;

    // ---- warp tiling ---------------------------------------------------------
    const int wm = (wid >> 1) * 16;          // 4 m-warps
    const int wn = (wid & 1)  * 8;           // 2 n-warps

    // ---- prefetch epilogue stats into regs (hidden under GEMM) --------------
    const int m0  = wm + (lane >> 2);
    const int kc0 = k0 + wn + (lane & 3) * 2;
    float x2v[2], p2v[2], pav[2], na2v[2];
    x2v[0] = g_x2[b0 + m0];
    x2v[1] = g_x2[b0 + m0 + 8];
    p2v[0] = g_p2[kc0];   p2v[1] = g_p2[kc0 + 1];
    pav[0] = g_pa[kc0];   pav[1] = g_pa[kc0 + 1];
    na2v[0] = g_na2[kc0]; na2v[1] = g_na2[kc0 + 1];

    // ---- cp.async loader: 3x 16B per thread per chunk ------------------------
    const int xr0 = tid >> 3,         xs0 = tid & 7;   // idx = tid
    const int xr1 = (256 + tid) >> 3, xs1 = tid & 7;   // idx = 256 + tid
    const __half* xh0 = g_xh + (size_t)(b0 + xr0) * DDIM + xs0 * 8;
    const __half* xh1 = g_xh + (size_t)(b0 + xr1) * DDIM + xs1 * 8;
    const uint32_t xd0 = XHOFF + xr0 * 128 + ((xs0 * 16) ^ ((xr0 & 7) << 4));
    const uint32_t xd1 = XHOFF + xr1 * 128 + ((xs1 * 16) ^ ((xr1 & 7) << 4));

    const int arr  = tid >> 7;            // 0: ph, 1: ah
    const int prow = (tid & 127) >> 3;    // 0..15
    const int pseg = tid & 7;
    const __half* basrc = (arr ? g_ah : g_ph) + (size_t)(k0 + prow) * DDIM + pseg * 8;
    const uint32_t badst = (arr ? AHOFF : PHOFF) + prow * 128
        + ((pseg * 16) ^ ((prow & 7) << 4));

    auto load_chunk = [&](int stage, int c) {
        const int c0 = c * KC;
        const uint32_t sb = smb + stage * STAGE;
        cp16(sb + xd0,   xh0 + c0);
        cp16(sb + xd1,   xh1 + c0);
        cp16(sb + badst, basrc + c0);
        CP_COMMIT();
    };

    // ---- ldsm addressing ------------------------------------------------------
    // A (x4): m16k16 per kstep
    const int g  = lane >> 3;
    const int r  = lane & 7;
    const int rowadd = (g & 1) * 8 + r;
    const int cadd   = (g >> 1) * 16;        // k8 byte offset
    const uint32_t axor  = (rowadd & 7) << 4;
    const uint32_t xterm = XHOFF + (wm + rowadd) * 128;
    // B combined (x4): mat0-1 = p (k0-7, k8-15), mat2-3 = a
    const int brow = lane & 7;
    const uint32_t bko  = (uint32_t)(g & 1) * 16;       // k8 select
    const uint32_t bxor = (uint32_t)brow << 4;
    const uint32_t bterm = PHOFF + (uint32_t)(g >> 1) * (AHOFF - PHOFF)
                         + (wn + brow) * 128;

    float accP[4] = {}, accA[4] = {};

    load_chunk(0, 0);
    load_chunk(1, 1);

    for (int c = 0; c < NCH; c++) {
        if (c < NCH - 1) CP_WAIT(1); else CP_WAIT(0);
        __syncthreads();   // chunk c visible; stage (c+2)%3 free (read 2 ago)

        if (c + 2 < NCH) load_chunk((c + 2) % 3, c + 2);   // right after sync

        const uint32_t sb = smb + (c % 3) * STAGE;
        #pragma unroll
        for (int ks2 = 0; ks2 < 2; ks2++) {
            // batch 2 ksteps of LDSM, then 4 MMAs
            uint32_t ax0[4], bp0[4], ax1[4], bp1[4];
            const uint32_t k0b = (uint32_t)(64 * ks2);
            ldsm_x4(ax0, sb + xterm + ((k0b + cadd) ^ axor));
            ldsm_x4(bp0, sb + bterm + ((k0b + bko) ^ bxor));
            ldsm_x4(ax1, sb + xterm + ((k0b + 32 + cadd) ^ axor));
            ldsm_x4(bp1, sb + bterm + ((k0b + 32 + bko) ^ bxor));
            mma_f16(accP, ax0, bp0[0], bp0[1]);
            mma_f16(accA, ax0, bp0[2], bp0[3]);
            mma_f16(accP, ax1, bp1[0], bp1[1]);
            mma_f16(accA, ax1, bp1[2], bp1[3]);
        }
    }

    // ---- epilogue: hyperbolic MLR logit (stats already in regs) --------------
    #pragma unroll
    for (int h = 0; h < 2; h++) {
        const int mloc = wm + h * 8 + (lane >> 2);
        const float x2 = x2v[h];
        const int kloc = wn + (lane & 3) * 2;
        float2 res;
        float* rr = (float*)&res;
        #pragma unroll
        for (int q = 0; q < 2; q++) {
            const float xp  = accP[h * 2 + q];
            const float xa  = accA[h * 2 + q];
            const float p2  = p2v[q];
            const float pa  = pav[q];
            const float na2 = na2v[q];

            float beta  = 1.f - p2;
            float alpha = -(1.f - 2.f * xp + x2);
            float den   = 1.f - 2.f * xp + p2 * x2 + EPS;
            float inv   = 1.f / den;
            float z2 = (alpha*alpha*p2 + 2.f*alpha*beta*xp + beta*beta*x2)
                       * inv * inv;
            float za = beta * (alpha * pa + beta * xa) * inv;
            float na = beta * sqrtf(na2);
            float lam = 2.f / (beta + EPS);
            float tt = 2.f * za / ((1.f - z2) * na + EPS);
            rr[q] = lam * na * asinhf(tt);
        }
        *(float2*)(out + (size_t)(b0 + mloc) * KK + k0 + kloc) = res;
    }
}

// ============================================================================
extern "C" void kernel_launch(void* const* d_in, const int* in_sizes, int n_in,
                              void* d_out, int out_size)
{
    const float* x = (const float*)d_in[0];
    const float* p = (const float*)d_in[1];
    const float* a = (const float*)d_in[2];
    float* out = (float*)d_out;

    conv_stats_kernel<<<(BB + KK) / 8, 256>>>(x, p, a);

    dim3 grid(KK / NT, BB / MT);    // (64, 8) = 512 CTAs
    hyp_hmma_kernel<<<grid, 256, SMEM2>>>(out);   // 36KB dynamic smem
}

// round 15
// speedup vs baseline: 1.2973x; 1.0025x over previous
#include <cuda_runtime.h>
#include <cuda_fp16.h>
#include <cstdint>

#define EPS  1e-6f
#define BB   512
#define KK   1024
#define DDIM 256

// ---------------- scratch (device globals: allocation-free) -----------------
__device__ __half g_xh[BB * DDIM];                    // fp16(x)
__device__ __half g_ph[KK * DDIM], g_ah[KK * DDIM];   // fp16(p), fp16(a)
__device__ float g_x2[BB], g_p2[KK], g_pa[KK], g_na2[KK];

// ---------------- helpers ----------------------------------------------------
__device__ __forceinline__ uint32_t smem_u32(const void* p) {
    uint32_t r;
    asm("{ .reg .u64 t; cvta.to.shared.u64 t, %1; cvt.u32.u64 %0, t; }"
        : "=r"(r) : "l"(p));
    return r;
}
__device__ __forceinline__ void ldsm_x4(uint32_t* r, uint32_t addr) {
    asm volatile("ldmatrix.sync.aligned.m8n8.x4.shared.b16 {%0,%1,%2,%3}, [%4];"
                 : "=r"(r[0]), "=r"(r[1]), "=r"(r[2]), "=r"(r[3]) : "r"(addr));
}
__device__ __forceinline__ void mma_f16(float* d, const uint32_t* a,
                                        uint32_t b0, uint32_t b1) {
    asm volatile(
        "mma.sync.aligned.m16n8k16.row.col.f32.f16.f16.f32 "
        "{%0,%1,%2,%3}, {%4,%5,%6,%7}, {%8,%9}, {%0,%1,%2,%3};"
        : "+f"(d[0]), "+f"(d[1]), "+f"(d[2]), "+f"(d[3])
        : "r"(a[0]), "r"(a[1]), "r"(a[2]), "r"(a[3]), "r"(b0), "r"(b1));
}
__device__ __forceinline__ void cp16(uint32_t dst, const void* src) {
    asm volatile("cp.async.cg.shared.global [%0], [%1], 16;"
                 :: "r"(dst), "l"(src) : "memory");
}
#define CP_COMMIT() asm volatile("cp.async.commit_group;" ::: "memory")
#define CP_WAIT(n)  asm volatile("cp.async.wait_group %0;" :: "n"(n) : "memory")

// ============================================================================
// Kernel 1: fp32 -> fp16 conversion + exact fp32 stats. One warp per row.
// ============================================================================
__device__ __forceinline__ uint32_t pack2h(float a, float b) {
    __half2 h = __floats2half2_rn(a, b);
    return *(uint32_t*)&h;
}

__global__ __launch_bounds__(256)
void conv_stats_kernel(const float* __restrict__ x,
                       const float* __restrict__ p,
                       const float* __restrict__ a)
{
    const int w    = blockIdx.x * 8 + (threadIdx.x >> 5);
    const int lane = threadIdx.x & 31;
    if (w < BB) {
        const int r = w;
        float f[8];
        *(float4*)&f[0] = *(const float4*)(x + r * DDIM + lane * 8);
        *(float4*)&f[4] = *(const float4*)(x + r * DDIM + lane * 8 + 4);
        uint4 hi;
        uint32_t* hv = (uint32_t*)&hi;
        float x2 = 0.f;
        #pragma unroll
        for (int i = 0; i < 4; i++) {
            hv[i] = pack2h(f[2*i], f[2*i+1]);
            x2 += f[2*i]*f[2*i] + f[2*i+1]*f[2*i+1];
        }
        *(uint4*)(g_xh + r * DDIM + lane * 8) = hi;
        #pragma unroll
        for (int m = 16; m; m >>= 1) x2 += __shfl_xor_sync(~0u, x2, m);
        if (lane == 0) g_x2[r] = x2;
    } else {
        const int r = w - BB;
        float fp[8], fa[8];
        *(float4*)&fp[0] = *(const float4*)(p + r * DDIM + lane * 8);
        *(float4*)&fp[4] = *(const float4*)(p + r * DDIM + lane * 8 + 4);
        *(float4*)&fa[0] = *(const float4*)(a + r * DDIM + lane * 8);
        *(float4*)&fa[4] = *(const float4*)(a + r * DDIM + lane * 8 + 4);
        uint4 hp, ha;
        uint32_t* pv = (uint32_t*)&hp;
        uint32_t* av = (uint32_t*)&ha;
        float p2 = 0.f, pa = 0.f, na2 = 0.f;
        #pragma unroll
        for (int i = 0; i < 4; i++) {
            pv[i] = pack2h(fp[2*i], fp[2*i+1]);
            av[i] = pack2h(fa[2*i], fa[2*i+1]);
            p2  += fp[2*i]*fp[2*i] + fp[2*i+1]*fp[2*i+1];
            pa  += fp[2*i]*fa[2*i] + fp[2*i+1]*fa[2*i+1];
            na2 += fa[2*i]*fa[2*i] + fa[2*i+1]*fa[2*i+1];
        }
        *(uint4*)(g_ph + r * DDIM + lane * 8) = hp;
        *(uint4*)(g_ah + r * DDIM + lane * 8) = ha;
        #pragma unroll
        for (int m = 16; m; m >>= 1) {
            p2  += __shfl_xor_sync(~0u, p2,  m);
            pa  += __shfl_xor_sync(~0u, pa,  m);
            na2 += __shfl_xor_sync(~0u, na2, m);
        }
        if (lane == 0) { g_p2[r] = p2; g_pa[r] = pa; g_na2[r] = na2; }
    }
}

// ============================================================================
// Kernel 2: dual fp16 GEMM (mma.sync), FULL-K single stage — no pipeline.
//   CTA: 64(m) x 16(n), 8 warps 4x2, warp tile 16x8. 512 CTAs, ~4/SM.
//   All of K=256 loaded at once: 4 chunk-blocks of 12KB = 48KB smem exactly.
//   ONE cp.async wait + ONE __syncthreads in the whole kernel.
// ============================================================================
#define MT    64
#define NT    16
#define KC    64
#define NCH   (DDIM / KC)   // 4
#define XHOFF 0
#define PHOFF 8192
#define AHOFF 10240
#define STAGE 12288
#define SMEM2 (4 * STAGE)   // 49152 = default smem limit exactly

__global__ __launch_bounds__(256)
void hyp_hmma_kernel(float* __restrict__ out)
{
    extern __shared__ char smem[];
    const uint32_t smb = smem_u32(smem);

    const int tid  = threadIdx.x;
    const int wid  = tid >> 5;
    const int lane = tid & 31;
    const int k0   = blockIdx.x * NT;
    const int b0   = blockIdx.y * MT;

    // ---- warp tiling ---------------------------------------------------------
    const int wm = (wid >> 1) * 16;          // 4 m-warps
    const int wn = (wid & 1)  * 8;           // 2 n-warps

    // ---- cp.async: load ALL of K at once (12 x 16B per thread) --------------
    const int xr0 = tid >> 3,         xs0 = tid & 7;   // idx = tid
    const int xr1 = (256 + tid) >> 3, xs1 = tid & 7;   // idx = 256 + tid
    const __half* xh0 = g_xh + (size_t)(b0 + xr0) * DDIM + xs0 * 8;
    const __half* xh1 = g_xh + (size_t)(b0 + xr1) * DDIM + xs1 * 8;
    const uint32_t xd0 = XHOFF + xr0 * 128 + ((xs0 * 16) ^ ((xr0 & 7) << 4));
    const uint32_t xd1 = XHOFF + xr1 * 128 + ((xs1 * 16) ^ ((xr1 & 7) << 4));

    const int arr  = tid >> 7;            // 0: ph, 1: ah
    const int prow = (tid & 127) >> 3;    // 0..15
    const int pseg = tid & 7;
    const __half* basrc = (arr ? g_ah : g_ph) + (size_t)(k0 + prow) * DDIM + pseg * 8;
    const uint32_t badst = (arr ? AHOFF : PHOFF) + prow * 128
        + ((pseg * 16) ^ ((prow & 7) << 4));

    #pragma unroll
    for (int c = 0; c < NCH; c++) {
        const int c0 = c * KC;
        const uint32_t sb = smb + c * STAGE;
        cp16(sb + xd0,   xh0 + c0);
        cp16(sb + xd1,   xh1 + c0);
        cp16(sb + badst, basrc + c0);
    }
    CP_COMMIT();

    // ---- prefetch epilogue stats into regs (overlaps cp.async) --------------
    const int m0  = wm + (lane >> 2);
    const int kc0 = k0 + wn + (lane & 3) * 2;
    float x2v[2], p2v[2], pav[2], na2v[2];
    x2v[0] = g_x2[b0 + m0];
    x2v[1] = g_x2[b0 + m0 + 8];
    p2v[0] = g_p2[kc0];   p2v[1] = g_p2[kc0 + 1];
    pav[0] = g_pa[kc0];   pav[1] = g_pa[kc0 + 1];
    na2v[0] = g_na2[kc0]; na2v[1] = g_na2[kc0 + 1];

    // ---- ldsm addressing ------------------------------------------------------
    const int g  = lane >> 3;
    const int r  = lane & 7;
    const int rowadd = (g & 1) * 8 + r;
    const int cadd   = (g >> 1) * 16;        // k8 byte offset
    const uint32_t axor  = (rowadd & 7) << 4;
    const uint32_t xterm = XHOFF + (wm + rowadd) * 128;
    const int brow = lane & 7;
    const uint32_t bko  = (uint32_t)(g & 1) * 16;       // k8 select
    const uint32_t bxor = (uint32_t)brow << 4;
    const uint32_t bterm = PHOFF + (uint32_t)(g >> 1) * (AHOFF - PHOFF)
                         + (wn + brow) * 128;

    float accP[4] = {}, accA[4] = {};

    CP_WAIT(0);
    __syncthreads();      // the ONLY barrier in the kernel

    #pragma unroll
    for (int c = 0; c < NCH; c++) {
        const uint32_t sb = smb + c * STAGE;
        #pragma unroll
        for (int ks2 = 0; ks2 < 2; ks2++) {
            uint32_t ax0[4], bp0[4], ax1[4], bp1[4];
            const uint32_t k0b = (uint32_t)(64 * ks2);
            ldsm_x4(ax0, sb + xterm + ((k0b + cadd) ^ axor));
            ldsm_x4(bp0, sb + bterm + ((k0b + bko) ^ bxor));
            ldsm_x4(ax1, sb + xterm + ((k0b + 32 + cadd) ^ axor));
            ldsm_x4(bp1, sb + bterm + ((k0b + 32 + bko) ^ bxor));
            mma_f16(accP, ax0, bp0[0], bp0[1]);
            mma_f16(accA, ax0, bp0[2], bp0[3]);
            mma_f16(accP, ax1, bp1[0], bp1[1]);
            mma_f16(accA, ax1, bp1[2], bp1[3]);
        }
    }

    // ---- epilogue: hyperbolic MLR logit (stats already in regs) --------------
    #pragma unroll
    for (int h = 0; h < 2; h++) {
        const int mloc = wm + h * 8 + (lane >> 2);
        const float x2 = x2v[h];
        const int kloc = wn + (lane & 3) * 2;
        float2 res;
        float* rr = (float*)&res;
        #pragma unroll
        for (int q = 0; q < 2; q++) {
            const float xp  = accP[h * 2 + q];
            const float xa  = accA[h * 2 + q];
            const float p2  = p2v[q];
            const float pa  = pav[q];
            const float na2 = na2v[q];

            float beta  = 1.f - p2;
            float alpha = -(1.f - 2.f * xp + x2);
            float den   = 1.f - 2.f * xp + p2 * x2 + EPS;
            float inv   = 1.f / den;
            float z2 = (alpha*alpha*p2 + 2.f*alpha*beta*xp + beta*beta*x2)
                       * inv * inv;
            float za = beta * (alpha * pa + beta * xa) * inv;
            float na = beta * sqrtf(na2);
            float lam = 2.f / (beta + EPS);
            float tt = 2.f * za / ((1.f - z2) * na + EPS);
            rr[q] = lam * na * asinhf(tt);
        }
        *(float2*)(out + (size_t)(b0 + mloc) * KK + k0 + kloc) = res;
    }
}

// ============================================================================
extern "C" void kernel_launch(void* const* d_in, const int* in_sizes, int n_in,
                              void* d_out, int out_size)
{
    const float* x = (const float*)d_in[0];
    const float* p = (const float*)d_in[1];
    const float* a = (const float*)d_in[2];
    float* out = (float*)d_out;

    conv_stats_kernel<<<(BB + KK) / 8, 256>>>(x, p, a);

    dim3 grid(KK / NT, BB / MT);    // (64, 8) = 512 CTAs
    hyp_hmma_kernel<<<grid, 256, SMEM2>>>(out);   // 48KB dynamic smem exactly
}

// round 16
// speedup vs baseline: 1.3233x; 1.0201x over previous
#include <cuda_runtime.h>
#include <cuda_fp16.h>
#include <cstdint>

#define EPS  1e-6f
#define BB   512
#define KK   1024
#define DDIM 256

// ---------------- scratch (device globals: allocation-free) -----------------
__device__ __half g_xh[BB * DDIM];                    // fp16(x)
__device__ __half g_ph[KK * DDIM], g_ah[KK * DDIM];   // fp16(p), fp16(a)
__device__ float g_x2[BB], g_p2[KK], g_pa[KK], g_na2[KK];
__device__ unsigned int g_ctr;                        // epoch counter (replay-safe)

// ---------------- helpers ----------------------------------------------------
__device__ __forceinline__ uint32_t smem_u32(const void* p) {
    uint32_t r;
    asm("{ .reg .u64 t; cvta.to.shared.u64 t, %1; cvt.u32.u64 %0, t; }"
        : "=r"(r) : "l"(p));
    return r;
}
__device__ __forceinline__ void ldsm_x4(uint32_t* r, uint32_t addr) {
    asm volatile("ldmatrix.sync.aligned.m8n8.x4.shared.b16 {%0,%1,%2,%3}, [%4];"
                 : "=r"(r[0]), "=r"(r[1]), "=r"(r[2]), "=r"(r[3]) : "r"(addr));
}
__device__ __forceinline__ void mma_f16(float* d, const uint32_t* a,
                                        uint32_t b0, uint32_t b1) {
    asm volatile(
        "mma.sync.aligned.m16n8k16.row.col.f32.f16.f16.f32 "
        "{%0,%1,%2,%3}, {%4,%5,%6,%7}, {%8,%9}, {%0,%1,%2,%3};"
        : "+f"(d[0]), "+f"(d[1]), "+f"(d[2]), "+f"(d[3])
        : "r"(a[0]), "r"(a[1]), "r"(a[2]), "r"(a[3]), "r"(b0), "r"(b1));
}
__device__ __forceinline__ void cp16(uint32_t dst, const void* src) {
    asm volatile("cp.async.cg.shared.global [%0], [%1], 16;"
                 :: "r"(dst), "l"(src) : "memory");
}
#define CP_COMMIT() asm volatile("cp.async.commit_group;" ::: "memory")
#define CP_WAIT(n)  asm volatile("cp.async.wait_group %0;" :: "n"(n) : "memory")

__device__ __forceinline__ uint32_t pack2h(float a, float b) {
    __half2 h = __floats2half2_rn(a, b);
    return *(uint32_t*)&h;
}

// ============================================================================
// FUSED kernel, single wave (512 CTAs, all co-resident: 4/SM x 148 = 592).
//   Phase 1: distributed fp32->fp16 conversion + stats (no redundancy).
//   Handshake: fence + atomic ticket + acquire-spin (epoch-based, replay-safe).
//   Phase 2: full-K dual fp16 GEMM (mma.sync) + fused hyperbolic epilogue.
// ============================================================================
#define MT    64
#define NT    16
#define KC    64
#define NCH   (DDIM / KC)   // 4
#define XHOFF 0
#define PHOFF 8192
#define AHOFF 10240
#define STAGE 12288
#define SMEM2 (4 * STAGE)   // 49152
#define NCTA  512

__global__ __launch_bounds__(256, 4)
void hyp_fused_kernel(const float* __restrict__ x,
                      const float* __restrict__ p,
                      const float* __restrict__ a,
                      float* __restrict__ out)
{
    extern __shared__ char smem[];
    __shared__ unsigned int s_go;
    const uint32_t smb = smem_u32(smem);

    const int tid  = threadIdx.x;
    const int wid  = tid >> 5;
    const int lane = tid & 31;
    const int k0   = blockIdx.x * NT;
    const int b0   = blockIdx.y * MT;
    const int cid  = blockIdx.y * gridDim.x + blockIdx.x;   // 0..511

    // ======================= Phase 1: conversion + stats =====================
    if (wid == 0) {
        // x row cid
        const int r = cid;
        float f[8];
        *(float4*)&f[0] = *(const float4*)(x + (size_t)r * DDIM + lane * 8);
        *(float4*)&f[4] = *(const float4*)(x + (size_t)r * DDIM + lane * 8 + 4);
        uint4 hi;
        uint32_t* hv = (uint32_t*)&hi;
        float x2 = 0.f;
        #pragma unroll
        for (int i = 0; i < 4; i++) {
            hv[i] = pack2h(f[2*i], f[2*i+1]);
            x2 += f[2*i]*f[2*i] + f[2*i+1]*f[2*i+1];
        }
        *(uint4*)(g_xh + (size_t)r * DDIM + lane * 8) = hi;
        #pragma unroll
        for (int m = 16; m; m >>= 1) x2 += __shfl_xor_sync(~0u, x2, m);
        if (lane == 0) g_x2[r] = x2;
    } else if (wid <= 2) {
        // p/a row pair
        const int r = 2 * cid + (wid - 1);
        float fp[8], fa[8];
        *(float4*)&fp[0] = *(const float4*)(p + (size_t)r * DDIM + lane * 8);
        *(float4*)&fp[4] = *(const float4*)(p + (size_t)r * DDIM + lane * 8 + 4);
        *(float4*)&fa[0] = *(const float4*)(a + (size_t)r * DDIM + lane * 8);
        *(float4*)&fa[4] = *(const float4*)(a + (size_t)r * DDIM + lane * 8 + 4);
        uint4 hp, ha;
        uint32_t* pv = (uint32_t*)&hp;
        uint32_t* av = (uint32_t*)&ha;
        float p2 = 0.f, pa = 0.f, na2 = 0.f;
        #pragma unroll
        for (int i = 0; i < 4; i++) {
            pv[i] = pack2h(fp[2*i], fp[2*i+1]);
            av[i] = pack2h(fa[2*i], fa[2*i+1]);
            p2  += fp[2*i]*fp[2*i] + fp[2*i+1]*fp[2*i+1];
            pa  += fp[2*i]*fa[2*i] + fp[2*i+1]*fa[2*i+1];
            na2 += fa[2*i]*fa[2*i] + fa[2*i+1]*fa[2*i+1];
        }
        *(uint4*)(g_ph + (size_t)r * DDIM + lane * 8) = hp;
        *(uint4*)(g_ah + (size_t)r * DDIM + lane * 8) = ha;
        #pragma unroll
        for (int m = 16; m; m >>= 1) {
            p2  += __shfl_xor_sync(~0u, p2,  m);
            pa  += __shfl_xor_sync(~0u, pa,  m);
            na2 += __shfl_xor_sync(~0u, na2, m);
        }
        if (lane == 0) { g_p2[r] = p2; g_pa[r] = pa; g_na2[r] = na2; }
    }
    __syncthreads();

    // ======================= handshake (epoch-based) =========================
    if (tid == 0) {
        __threadfence();                               // publish CTA's writes
        unsigned int t = atomicAdd(&g_ctr, 1u);
        unsigned int target = (t / NCTA + 1u) * NCTA;  // end of this epoch
        unsigned int v;
        do {
            asm volatile("ld.acquire.gpu.global.b32 %0, [%1];"
                         : "=r"(v) : "l"(&g_ctr));
        } while (v < target);
        s_go = v;
    }
    __syncthreads();
    (void)s_go;

    // ======================= Phase 2: full-K GEMM ============================
    const int wm = (wid >> 1) * 16;          // 4 m-warps
    const int wn = (wid & 1)  * 8;           // 2 n-warps

    // cp.async: load ALL of K at once (12 x 16B per thread)
    const int xr0 = tid >> 3,         xs0 = tid & 7;
    const int xr1 = (256 + tid) >> 3, xs1 = tid & 7;
    const __half* xh0 = g_xh + (size_t)(b0 + xr0) * DDIM + xs0 * 8;
    const __half* xh1 = g_xh + (size_t)(b0 + xr1) * DDIM + xs1 * 8;
    const uint32_t xd0 = XHOFF + xr0 * 128 + ((xs0 * 16) ^ ((xr0 & 7) << 4));
    const uint32_t xd1 = XHOFF + xr1 * 128 + ((xs1 * 16) ^ ((xr1 & 7) << 4));

    const int arr  = tid >> 7;            // 0: ph, 1: ah
    const int prow = (tid & 127) >> 3;    // 0..15
    const int pseg = tid & 7;
    const __half* basrc = (arr ? g_ah : g_ph) + (size_t)(k0 + prow) * DDIM + pseg * 8;
    const uint32_t badst = (arr ? AHOFF : PHOFF) + prow * 128
        + ((pseg * 16) ^ ((prow & 7) << 4));

    #pragma unroll
    for (int c = 0; c < NCH; c++) {
        const int c0 = c * KC;
        const uint32_t sb = smb + c * STAGE;
        cp16(sb + xd0,   xh0 + c0);
        cp16(sb + xd1,   xh1 + c0);
        cp16(sb + badst, basrc + c0);
    }
    CP_COMMIT();

    // prefetch epilogue stats into regs (overlaps cp.async)
    const int m0  = wm + (lane >> 2);
    const int kc0 = k0 + wn + (lane & 3) * 2;
    float x2v[2], p2v[2], pav[2], na2v[2];
    x2v[0] = g_x2[b0 + m0];
    x2v[1] = g_x2[b0 + m0 + 8];
    p2v[0] = g_p2[kc0];   p2v[1] = g_p2[kc0 + 1];
    pav[0] = g_pa[kc0];   pav[1] = g_pa[kc0 + 1];
    na2v[0] = g_na2[kc0]; na2v[1] = g_na2[kc0 + 1];

    // ldsm addressing
    const int g  = lane >> 3;
    const int r  = lane & 7;
    const int rowadd = (g & 1) * 8 + r;
    const int cadd   = (g >> 1) * 16;
    const uint32_t axor  = (rowadd & 7) << 4;
    const uint32_t xterm = XHOFF + (wm + rowadd) * 128;
    const int brow = lane & 7;
    const uint32_t bko  = (uint32_t)(g & 1) * 16;
    const uint32_t bxor = (uint32_t)brow << 4;
    const uint32_t bterm = PHOFF + (uint32_t)(g >> 1) * (AHOFF - PHOFF)
                         + (wn + brow) * 128;

    float accP[4] = {}, accA[4] = {};

    CP_WAIT(0);
    __syncthreads();

    #pragma unroll
    for (int c = 0; c < NCH; c++) {
        const uint32_t sb = smb + c * STAGE;
        #pragma unroll
        for (int ks2 = 0; ks2 < 2; ks2++) {
            uint32_t ax0[4], bp0[4], ax1[4], bp1[4];
            const uint32_t k0b = (uint32_t)(64 * ks2);
            ldsm_x4(ax0, sb + xterm + ((k0b + cadd) ^ axor));
            ldsm_x4(bp0, sb + bterm + ((k0b + bko) ^ bxor));
            ldsm_x4(ax1, sb + xterm + ((k0b + 32 + cadd) ^ axor));
            ldsm_x4(bp1, sb + bterm + ((k0b + 32 + bko) ^ bxor));
            mma_f16(accP, ax0, bp0[0], bp0[1]);
            mma_f16(accA, ax0, bp0[2], bp0[3]);
            mma_f16(accP, ax1, bp1[0], bp1[1]);
            mma_f16(accA, ax1, bp1[2], bp1[3]);
        }
    }

    // epilogue: hyperbolic MLR logit
    #pragma unroll
    for (int h = 0; h < 2; h++) {
        const int mloc = wm + h * 8 + (lane >> 2);
        const float x2 = x2v[h];
        const int kloc = wn + (lane & 3) * 2;
        float2 res;
        float* rr = (float*)&res;
        #pragma unroll
        for (int q = 0; q < 2; q++) {
            const float xp  = accP[h * 2 + q];
            const float xa  = accA[h * 2 + q];
            const float p2  = p2v[q];
            const float pa  = pav[q];
            const float na2 = na2v[q];

            float beta  = 1.f - p2;
            float alpha = -(1.f - 2.f * xp + x2);
            float den   = 1.f - 2.f * xp + p2 * x2 + EPS;
            float inv   = 1.f / den;
            float z2 = (alpha*alpha*p2 + 2.f*alpha*beta*xp + beta*beta*x2)
                       * inv * inv;
            float za = beta * (alpha * pa + beta * xa) * inv;
            float na = beta * sqrtf(na2);
            float lam = 2.f / (beta + EPS);
            float tt = 2.f * za / ((1.f - z2) * na + EPS);
            rr[q] = lam * na * asinhf(tt);
        }
        *(float2*)(out + (size_t)(b0 + mloc) * KK + k0 + kloc) = res;
    }
}

// ============================================================================
extern "C" void kernel_launch(void* const* d_in, const int* in_sizes, int n_in,
                              void* d_out, int out_size)
{
    const float* x = (const float*)d_in[0];
    const float* p = (const float*)d_in[1];
    const float* a = (const float*)d_in[2];
    float* out = (float*)d_out;

    static bool attr_done = false;
    if (!attr_done) {
        cudaFuncSetAttribute(hyp_fused_kernel,
                             cudaFuncAttributeMaxDynamicSharedMemorySize, SMEM2);
        attr_done = true;
    }
    dim3 grid(KK / NT, BB / MT);    // (64, 8) = 512 CTAs, single co-resident wave
    hyp_fused_kernel<<<grid, 256, SMEM2>>>(x, p, a, out);
}

// round 17
// speedup vs baseline: 1.5808x; 1.1946x over previous
#include <cuda_runtime.h>
#include <cuda_fp16.h>
#include <cstdint>

#define EPS  1e-6f
#define BB   512
#define KK   1024
#define DDIM 256

// ---------------- scratch (device globals: allocation-free) -----------------
__device__ __half g_xh[BB * DDIM];                    // fp16(x)
__device__ __half g_ph[KK * DDIM], g_ah[KK * DDIM];   // fp16(p), fp16(a)
__device__ float g_x2[BB], g_p2[KK], g_pa[KK], g_na2[KK];
__device__ unsigned int g_ctr;                        // epoch counter (replay-safe)

// ---------------- helpers ----------------------------------------------------
__device__ __forceinline__ uint32_t smem_u32(const void* p) {
    uint32_t r;
    asm("{ .reg .u64 t; cvta.to.shared.u64 t, %1; cvt.u32.u64 %0, t; }"
        : "=r"(r) : "l"(p));
    return r;
}
__device__ __forceinline__ void ldsm_x4(uint32_t* r, uint32_t addr) {
    asm volatile("ldmatrix.sync.aligned.m8n8.x4.shared.b16 {%0,%1,%2,%3}, [%4];"
                 : "=r"(r[0]), "=r"(r[1]), "=r"(r[2]), "=r"(r[3]) : "r"(addr));
}
__device__ __forceinline__ void mma_f16(float* d, const uint32_t* a,
                                        uint32_t b0, uint32_t b1) {
    asm volatile(
        "mma.sync.aligned.m16n8k16.row.col.f32.f16.f16.f32 "
        "{%0,%1,%2,%3}, {%4,%5,%6,%7}, {%8,%9}, {%0,%1,%2,%3};"
        : "+f"(d[0]), "+f"(d[1]), "+f"(d[2]), "+f"(d[3])
        : "r"(a[0]), "r"(a[1]), "r"(a[2]), "r"(a[3]), "r"(b0), "r"(b1));
}
__device__ __forceinline__ void cp16(uint32_t dst, const void* src) {
    asm volatile("cp.async.cg.shared.global [%0], [%1], 16;"
                 :: "r"(dst), "l"(src) : "memory");
}
#define CP_COMMIT() asm volatile("cp.async.commit_group;" ::: "memory")
#define CP_WAIT(n)  asm volatile("cp.async.wait_group %0;" :: "n"(n) : "memory")

__device__ __forceinline__ uint32_t pack2h(float a, float b) {
    __half2 h = __floats2half2_rn(a, b);
    return *(uint32_t*)&h;
}

// ============================================================================
// FUSED kernel, single wave (256 CTAs, all co-resident: 3/SM x 148 = 444).
//   Phase 1: distributed fp32->fp16 conversion + stats (6 of 8 warps active).
//   Handshake: fence + atomic ticket + acquire-spin (epoch-based, replay-safe).
//   Phase 2: full-K dual fp16 GEMM, CTA tile 64(m) x 32(n), warp tile 16x16.
//   Smem 64KB: 4 chunk-blocks of [X 8K | P 4K | A 4K].
// ============================================================================
#define MT    64
#define NT    32
#define KC    64
#define NCH   (DDIM / KC)   // 4
#define XHOFF 0
#define PHOFF 8192
#define AHOFF 12288
#define STAGE 16384
#define SMEM2 (4 * STAGE)   // 65536 (opt-in)
#define NCTA  256

__global__ __launch_bounds__(256, 3)
void hyp_fused_kernel(const float* __restrict__ x,
                      const float* __restrict__ p,
                      const float* __restrict__ a,
                      float* __restrict__ out)
{
    extern __shared__ char smem[];
    __shared__ unsigned int s_go;
    const uint32_t smb = smem_u32(smem);

    const int tid  = threadIdx.x;
    const int wid  = tid >> 5;
    const int lane = tid & 31;
    const int k0   = blockIdx.x * NT;
    const int b0   = blockIdx.y * MT;
    const int cid  = blockIdx.y * gridDim.x + blockIdx.x;   // 0..255

    // ======================= Phase 1: conversion + stats =====================
    if (wid < 2) {
        // x rows 2*cid, 2*cid+1
        const int r = 2 * cid + wid;
        float f[8];
        *(float4*)&f[0] = *(const float4*)(x + (size_t)r * DDIM + lane * 8);
        *(float4*)&f[4] = *(const float4*)(x + (size_t)r * DDIM + lane * 8 + 4);
        uint4 hi;
        uint32_t* hv = (uint32_t*)&hi;
        float x2 = 0.f;
        #pragma unroll
        for (int i = 0; i < 4; i++) {
            hv[i] = pack2h(f[2*i], f[2*i+1]);
            x2 += f[2*i]*f[2*i] + f[2*i+1]*f[2*i+1];
        }
        *(uint4*)(g_xh + (size_t)r * DDIM + lane * 8) = hi;
        #pragma unroll
        for (int m = 16; m; m >>= 1) x2 += __shfl_xor_sync(~0u, x2, m);
        if (lane == 0) g_x2[r] = x2;
    } else if (wid < 6) {
        // p/a rows 4*cid .. 4*cid+3
        const int r = 4 * cid + (wid - 2);
        float fp[8], fa[8];
        *(float4*)&fp[0] = *(const float4*)(p + (size_t)r * DDIM + lane * 8);
        *(float4*)&fp[4] = *(const float4*)(p + (size_t)r * DDIM + lane * 8 + 4);
        *(float4*)&fa[0] = *(const float4*)(a + (size_t)r * DDIM + lane * 8);
        *(float4*)&fa[4] = *(const float4*)(a + (size_t)r * DDIM + lane * 8 + 4);
        uint4 hp, ha;
        uint32_t* pv = (uint32_t*)&hp;
        uint32_t* av = (uint32_t*)&ha;
        float p2 = 0.f, pa = 0.f, na2 = 0.f;
        #pragma unroll
        for (int i = 0; i < 4; i++) {
            pv[i] = pack2h(fp[2*i], fp[2*i+1]);
            av[i] = pack2h(fa[2*i], fa[2*i+1]);
            p2  += fp[2*i]*fp[2*i] + fp[2*i+1]*fp[2*i+1];
            pa  += fp[2*i]*fa[2*i] + fp[2*i+1]*fa[2*i+1];
            na2 += fa[2*i]*fa[2*i] + fa[2*i+1]*fa[2*i+1];
        }
        *(uint4*)(g_ph + (size_t)r * DDIM + lane * 8) = hp;
        *(uint4*)(g_ah + (size_t)r * DDIM + lane * 8) = ha;
        #pragma unroll
        for (int m = 16; m; m >>= 1) {
            p2  += __shfl_xor_sync(~0u, p2,  m);
            pa  += __shfl_xor_sync(~0u, pa,  m);
            na2 += __shfl_xor_sync(~0u, na2, m);
        }
        if (lane == 0) { g_p2[r] = p2; g_pa[r] = pa; g_na2[r] = na2; }
    }
    __syncthreads();

    // ======================= handshake (epoch-based) =========================
    if (tid == 0) {
        __threadfence();                               // publish CTA's writes
        unsigned int t = atomicAdd(&g_ctr, 1u);
        unsigned int target = (t / NCTA + 1u) * NCTA;  // end of this epoch
        unsigned int v;
        do {
            asm volatile("ld.acquire.gpu.global.b32 %0, [%1];"
                         : "=r"(v) : "l"(&g_ctr));
        } while (v < target);
        s_go = v;
    }
    __syncthreads();
    (void)s_go;

    // ======================= Phase 2: full-K GEMM ============================
    const int wm = (wid >> 1) * 16;          // 4 m-warps
    const int wn = (wid & 1)  * 16;          // 2 n-warps, 16 cols each

    // cp.async: load ALL of K at once (16 x 16B per thread)
    const int xr0 = tid >> 3,         xs0 = tid & 7;
    const int xr1 = (256 + tid) >> 3, xs1 = tid & 7;
    const __half* xh0 = g_xh + (size_t)(b0 + xr0) * DDIM + xs0 * 8;
    const __half* xh1 = g_xh + (size_t)(b0 + xr1) * DDIM + xs1 * 8;
    const uint32_t xd0 = XHOFF + xr0 * 128 + ((xs0 * 16) ^ ((xr0 & 7) << 4));
    const uint32_t xd1 = XHOFF + xr1 * 128 + ((xs1 * 16) ^ ((xr1 & 7) << 4));

    const int prow = tid >> 3;            // 0..31
    const int pseg = tid & 7;
    const __half* psrc = g_ph + (size_t)(k0 + prow) * DDIM + pseg * 8;
    const __half* asrc = g_ah + (size_t)(k0 + prow) * DDIM + pseg * 8;
    const uint32_t pad = prow * 128 + ((pseg * 16) ^ ((prow & 7) << 4));

    #pragma unroll
    for (int c = 0; c < NCH; c++) {
        const int c0 = c * KC;
        const uint32_t sb = smb + c * STAGE;
        cp16(sb + XHOFF + xd0, xh0 + c0);
        cp16(sb + XHOFF + xd1, xh1 + c0);
        cp16(sb + PHOFF + pad, psrc + c0);
        cp16(sb + AHOFF + pad, asrc + c0);
    }
    CP_COMMIT();

    // prefetch epilogue stats into regs (overlaps cp.async)
    const int m0  = wm + (lane >> 2);
    const int kcb = k0 + wn + (lane & 3) * 2;
    float x2v[2], p2v[4], pav[4], na2v[4];
    x2v[0] = g_x2[b0 + m0];
    x2v[1] = g_x2[b0 + m0 + 8];
    #pragma unroll
    for (int j = 0; j < 2; j++) {
        p2v[j*2+0]  = g_p2[kcb + j*8];   p2v[j*2+1]  = g_p2[kcb + j*8 + 1];
        pav[j*2+0]  = g_pa[kcb + j*8];   pav[j*2+1]  = g_pa[kcb + j*8 + 1];
        na2v[j*2+0] = g_na2[kcb + j*8];  na2v[j*2+1] = g_na2[kcb + j*8 + 1];
    }

    // ldsm addressing (A and B use the same lane geometry)
    const int g  = lane >> 3;
    const int r  = lane & 7;
    const int rowadd = (g & 1) * 8 + r;       // 0..15
    const int cadd   = (g >> 1) * 16;         // k8 byte offset
    const uint32_t kxor  = (rowadd & 7) << 4;
    const uint32_t xterm = XHOFF + (wm + rowadd) * 128;
    const uint32_t pterm = PHOFF + (wn + rowadd) * 128;
    const uint32_t aterm = AHOFF + (wn + rowadd) * 128;

    float accP[2][4] = {}, accA[2][4] = {};

    CP_WAIT(0);
    __syncthreads();      // the only phase-2 barrier

    #pragma unroll
    for (int c = 0; c < NCH; c++) {
        const uint32_t sb = smb + c * STAGE;
        #pragma unroll
        for (int ks = 0; ks < 4; ks++) {
            const uint32_t koff = ((uint32_t)(32 * ks + cadd)) ^ kxor;
            uint32_t ax[4], bp[4], ba[4];
            ldsm_x4(ax, sb + xterm + koff);
            ldsm_x4(bp, sb + pterm + koff);
            ldsm_x4(ba, sb + aterm + koff);
            // mats: 0:(n0-7,k0-7) 1:(n8-15,k0-7) 2:(n0-7,k8-15) 3:(n8-15,k8-15)
            mma_f16(accP[0], ax, bp[0], bp[2]);
            mma_f16(accP[1], ax, bp[1], bp[3]);
            mma_f16(accA[0], ax, ba[0], ba[2]);
            mma_f16(accA[1], ax, ba[1], ba[3]);
        }
    }

    // epilogue: hyperbolic MLR logit (fast asinh)
    #pragma unroll
    for (int h = 0; h < 2; h++) {
        const int mloc = wm + h * 8 + (lane >> 2);
        const float x2 = x2v[h];
        #pragma unroll
        for (int j = 0; j < 2; j++) {
            const int kloc = wn + j * 8 + (lane & 3) * 2;
            float2 res;
            float* rr = (float*)&res;
            #pragma unroll
            for (int q = 0; q < 2; q++) {
                const float xp  = accP[j][h * 2 + q];
                const float xa  = accA[j][h * 2 + q];
                const float p2  = p2v[j*2+q];
                const float pa  = pav[j*2+q];
                const float na2 = na2v[j*2+q];

                float beta  = 1.f - p2;
                float alpha = -(1.f - 2.f * xp + x2);
                float den   = 1.f - 2.f * xp + p2 * x2 + EPS;
                float inv   = 1.f / den;
                float z2 = (alpha*alpha*p2 + 2.f*alpha*beta*xp + beta*beta*x2)
                           * inv * inv;
                float za = beta * (alpha * pa + beta * xa) * inv;
                float na = beta * sqrtf(na2);
                float lam = 2.f / (beta + EPS);
                float tt = 2.f * za / ((1.f - z2) * na + EPS);
                // fast asinh: sign(t) * log(|t| + sqrt(t^2+1)), arg >= 1
                float at = fabsf(tt);
                float s  = __logf(at + __fsqrt_rn(__fmaf_rn(at, at, 1.f)));
                rr[q] = copysignf(lam * na * s, tt);
            }
            *(float2*)(out + (size_t)(b0 + mloc) * KK + k0 + kloc) = res;
        }
    }
}

// ============================================================================
extern "C" void kernel_launch(void* const* d_in, const int* in_sizes, int n_in,
                              void* d_out, int out_size)
{
    const float* x = (const float*)d_in[0];
    const float* p = (const float*)d_in[1];
    const float* a = (const float*)d_in[2];
    float* out = (float*)d_out;

    cudaFuncSetAttribute(hyp_fused_kernel,
                         cudaFuncAttributeMaxDynamicSharedMemorySize, SMEM2);
    dim3 grid(KK / NT, BB / MT);    // (32, 8) = 256 CTAs, single co-resident wave
    hyp_fused_kernel<<<grid, 256, SMEM2>>>(x, p, a, out);
}